// round 6
// baseline (speedup 1.0000x reference)
#include <cuda_runtime.h>
#include <math_constants.h>

// Problem constants
#define BB 16
#define MM 4096
#define TT 4
#define DD 256
#define VV 40000
#define CONV 512
#define BD (BB*DD)          // 4096
#define BM (BB*MM)          // 65536
#define ECHUNK 32           // rows per embed block
#define NEB (MM/ECHUNK)     // 128 embed blocks per batch
#define OCHUNK 32           // rows per k_o block
#define NOB (MM/OCHUNK)     // 128 o blocks per batch
#define LBLK 64             // rows per logit block
#define NLB (MM/LBLK)       // 64 logit blocks per batch
#define EMB_SZ ((size_t)BB*MM*DD)  // 16777216 elements (64MB)

// ---------------- device scratch (allocation-free) ----------------
__device__ float g_emb[2*16777216];      // emb[1],emb[2]; emb[3] lives in d_out; emb[0] never materialized
__device__ float g_logit[BM];
__device__ float g_uf[BD];
__device__ float g_part[NOB*BD];         // deterministic partial sums for o_k
__device__ float g_pmax[BB*NLB];
__device__ float g_psum[BB*NLB];
__device__ float g_smax[BB];
__device__ float g_sinv[BB];
__device__ float g_tdot[BB*VV];          // tdot[b][v] = C0[v]·uf_b
__device__ float g_hdot[BB*CONV];        // hdot[b][r] = hist[b,r]·uf_b

// ---------------- kernels ----------------

// emb[h][b,m,:] = sum_t C[h][story[b,m,t],:] (+ history in conv window)
// slot: 0 -> g_emb[0], 1 -> g_emb[1], 2 -> emb3 (d_out). stream=1 -> __stcs stores.
__global__ void __launch_bounds__(256) k_embed(
        int slot, int stream, const int* __restrict__ story, const int* __restrict__ kb_len,
        const int* __restrict__ conv_len, const float* __restrict__ hist,
        const float* __restrict__ table, float* __restrict__ emb3){
    int b = blockIdx.y;
    int m0 = blockIdx.x * ECHUNK;
    int mg = threadIdx.x >> 6;        // 0..3
    int d4 = threadIdx.x & 63;        // float4 lane
    int start = kb_len[b], clen = conv_len[b];
    float* dst = ((slot < 2) ? (g_emb + (size_t)slot*EMB_SZ) : emb3) + (size_t)b*MM*DD;
    const float4* hb = reinterpret_cast<const float4*>(hist + (size_t)b*CONV*DD);
    const float4* t4 = reinterpret_cast<const float4*>(table);
    #pragma unroll 2
    for(int mi = 0; mi < ECHUNK; mi += 8){
        int mA = m0 + mi + mg;
        int mB = mA + 4;
        int4 ta = *reinterpret_cast<const int4*>(story + (size_t)(b*MM + mA)*TT);
        int4 tb = *reinterpret_cast<const int4*>(story + (size_t)(b*MM + mB)*TT);
        float4 a0 = t4[(size_t)ta.x*64 + d4];
        float4 a1 = t4[(size_t)ta.y*64 + d4];
        float4 a2 = t4[(size_t)ta.z*64 + d4];
        float4 a3 = t4[(size_t)ta.w*64 + d4];
        float4 b0 = t4[(size_t)tb.x*64 + d4];
        float4 b1 = t4[(size_t)tb.y*64 + d4];
        float4 b2 = t4[(size_t)tb.z*64 + d4];
        float4 b3 = t4[(size_t)tb.w*64 + d4];
        float4 accA, accB;
        accA.x = a0.x + a1.x + a2.x + a3.x;
        accA.y = a0.y + a1.y + a2.y + a3.y;
        accA.z = a0.z + a1.z + a2.z + a3.z;
        accA.w = a0.w + a1.w + a2.w + a3.w;
        accB.x = b0.x + b1.x + b2.x + b3.x;
        accB.y = b0.y + b1.y + b2.y + b3.y;
        accB.z = b0.z + b1.z + b2.z + b3.z;
        accB.w = b0.w + b1.w + b2.w + b3.w;
        int rA = mA - start;
        if (rA >= 0 && rA < clen){
            float4 hv = hb[(size_t)rA*64 + d4];
            accA.x += hv.x; accA.y += hv.y; accA.z += hv.z; accA.w += hv.w;
        }
        int rB = mB - start;
        if (rB >= 0 && rB < clen){
            float4 hv = hb[(size_t)rB*64 + d4];
            accB.x += hv.x; accB.y += hv.y; accB.z += hv.z; accB.w += hv.w;
        }
        float4* pA = reinterpret_cast<float4*>(dst + (size_t)mA*DD) + d4;
        float4* pB = reinterpret_cast<float4*>(dst + (size_t)mB*DD) + d4;
        if (stream){ __stcs(pA, accA); __stcs(pB, accB); }
        else       { *pA = accA; *pB = accB; }
    }
}

// init uf = query_vector
__global__ void k_init(const float* __restrict__ qv){
    g_uf[blockIdx.x*DD + threadIdx.x] = qv[blockIdx.x*DD + threadIdx.x];
}

// tdot[b][v] = table0[v]·uf[b]. Warp handles 8 rows × one half (8 b's) at a time.
__global__ void __launch_bounds__(256) k_tdot(const float* __restrict__ table){
    __shared__ float suf[16][260];
    int t = threadIdx.x;
    for(int i = t; i < 16*256; i += 256) suf[i>>8][i&255] = g_uf[i];
    __syncthreads();
    int warp = t >> 5, lane = t & 31;
    int r0 = (blockIdx.x*8 + warp)*8;          // grid 625 blocks -> 5000 warps -> rows [0,40000)
    int d0 = lane*8;
    #pragma unroll
    for(int half = 0; half < 2; ++half){
        float ufr[8][8];
        #pragma unroll
        for(int bb = 0; bb < 8; ++bb)
            #pragma unroll
            for(int i = 0; i < 8; ++i) ufr[bb][i] = suf[half*8 + bb][d0 + i];
        for(int r = r0; r < r0 + 8; ++r){
            const float4* row = reinterpret_cast<const float4*>(table + (size_t)r*DD);
            float4 v0 = row[lane*2], v1 = row[lane*2 + 1];
            float tv[8] = {v0.x, v0.y, v0.z, v0.w, v1.x, v1.y, v1.z, v1.w};
            float acc[8];
            #pragma unroll
            for(int bb = 0; bb < 8; ++bb){
                float a = 0.f;
                #pragma unroll
                for(int i = 0; i < 8; ++i) a += tv[i]*ufr[bb][i];
                acc[bb] = a;
            }
            #pragma unroll
            for(int off = 16; off; off >>= 1)
                #pragma unroll
                for(int bb = 0; bb < 8; ++bb)
                    acc[bb] += __shfl_xor_sync(0xffffffffu, acc[bb], off);
            if (lane == 0){
                #pragma unroll
                for(int bb = 0; bb < 8; ++bb)
                    g_tdot[(size_t)(half*8 + bb)*VV + r] = acc[bb];
            }
        }
    }
}

// hdot[b][r] = hist[b,r]·uf[b]
__global__ void __launch_bounds__(256) k_hdot(const float* __restrict__ hist){
    int b = blockIdx.x;
    int warp = threadIdx.x >> 5, lane = threadIdx.x & 31;
    int d0 = lane*8;
    float ufr[8];
    #pragma unroll
    for(int i = 0; i < 8; ++i) ufr[i] = g_uf[b*DD + d0 + i];
    for(int r = warp; r < CONV; r += 8){
        const float4* row = reinterpret_cast<const float4*>(hist + ((size_t)b*CONV + r)*DD);
        float4 v0 = row[lane*2], v1 = row[lane*2 + 1];
        float a = v0.x*ufr[0] + v0.y*ufr[1] + v0.z*ufr[2] + v0.w*ufr[3]
                + v1.x*ufr[4] + v1.y*ufr[5] + v1.z*ufr[6] + v1.w*ufr[7];
        #pragma unroll
        for(int off = 16; off; off >>= 1) a += __shfl_down_sync(0xffffffffu, a, off);
        if (lane == 0) g_hdot[b*CONV + r] = a;
    }
}

// hop0 logits via tdot gather: logit = gp * (Σ_t tdot[tok] + hdot window)
__global__ void __launch_bounds__(64) k_logit_fast(
        const int* __restrict__ story, const int* __restrict__ kb_len,
        const int* __restrict__ conv_len, const float* __restrict__ gp){
    int b = blockIdx.y;
    int m = blockIdx.x*64 + threadIdx.x;
    const float* td = g_tdot + (size_t)b*VV;
    int4 tok = *reinterpret_cast<const int4*>(story + (size_t)(b*MM + m)*TT);
    float v = td[tok.x] + td[tok.y] + td[tok.z] + td[tok.w];
    int r = m - kb_len[b];
    if (r >= 0 && r < conv_len[b]) v += g_hdot[b*CONV + r];
    v *= gp[b*MM + m];
    g_logit[b*MM + m] = v;
    // block online-softmax partials over 64 values (2 warps)
    __shared__ float smax[2], ssum[2];
    int lane = threadIdx.x & 31, warp = threadIdx.x >> 5;
    float mx = v;
    #pragma unroll
    for(int off = 16; off; off >>= 1) mx = fmaxf(mx, __shfl_xor_sync(0xffffffffu, mx, off));
    float sm = expf(v - mx);
    #pragma unroll
    for(int off = 16; off; off >>= 1) sm += __shfl_xor_sync(0xffffffffu, sm, off);
    if (lane == 0){ smax[warp] = mx; ssum[warp] = sm; }
    __syncthreads();
    if (threadIdx.x == 0){
        float m2 = fmaxf(smax[0], smax[1]);
        float s2 = ssum[0]*expf(smax[0] - m2) + ssum[1]*expf(smax[1] - m2);
        g_pmax[b*NLB + blockIdx.x] = m2;
        g_psum[b*NLB + blockIdx.x] = s2;
    }
}

// streaming logits (hops 1,2): emb slot 0/1 read from g_emb (expected L2-hot after o pass)
__global__ void __launch_bounds__(256) k_logit(
        int slot, const float* __restrict__ gp, float* __restrict__ out_ext){
    int b = blockIdx.y;
    const float* emb = g_emb + (size_t)slot*EMB_SZ;
    const float* u = g_uf + b*DD;
    __shared__ float4 su[DD/4];
    __shared__ float smax[8], ssum[8];
    if (threadIdx.x < DD/4) su[threadIdx.x] = reinterpret_cast<const float4*>(u)[threadIdx.x];
    __syncthreads();
    int warp = threadIdx.x >> 5, lane = threadIdx.x & 31;
    int mbase = blockIdx.x*LBLK + warp*8;
    float lv[8];
    #pragma unroll
    for(int i = 0; i < 8; ++i){
        int m = mbase + i;
        const float4* row = reinterpret_cast<const float4*>(emb + ((size_t)b*MM + m)*DD);
        float4 v0 = row[lane], v1 = row[lane + 32];
        float4 u0 = su[lane], u1 = su[lane + 32];
        float acc = v0.x*u0.x + v0.y*u0.y + v0.z*u0.z + v0.w*u0.w
                  + v1.x*u1.x + v1.y*u1.y + v1.z*u1.z + v1.w*u1.w;
        #pragma unroll
        for(int off = 16; off; off >>= 1) acc += __shfl_down_sync(0xffffffffu, acc, off);
        if (lane == 0) acc *= gp[b*MM + m];
        lv[i] = acc;
    }
    if (lane == 0){
        float mx = lv[0];
        #pragma unroll
        for(int i = 1; i < 8; ++i) mx = fmaxf(mx, lv[i]);
        float sm = 0.f;
        #pragma unroll
        for(int i = 0; i < 8; ++i){
            g_logit[b*MM + mbase + i] = lv[i];
            if (out_ext) out_ext[b*MM + mbase + i] = lv[i];
            sm += expf(lv[i] - mx);
        }
        smax[warp] = mx; ssum[warp] = sm;
    }
    __syncthreads();
    if (threadIdx.x == 0){
        float mx = smax[0];
        #pragma unroll
        for(int w = 1; w < 8; ++w) mx = fmaxf(mx, smax[w]);
        float sm = 0.f;
        #pragma unroll
        for(int w = 0; w < 8; ++w) sm += ssum[w]*expf(smax[w] - mx);
        g_pmax[b*NLB + blockIdx.x] = mx;
        g_psum[b*NLB + blockIdx.x] = sm;
    }
}

// combine per-block softmax partials (64 per batch): warp w = batch b
__global__ void __launch_bounds__(512) k_stats(){
    int w = threadIdx.x >> 5, lane = threadIdx.x & 31;
    float m0 = g_pmax[w*NLB + lane], m1 = g_pmax[w*NLB + lane + 32];
    float s0 = g_psum[w*NLB + lane], s1 = g_psum[w*NLB + lane + 32];
    float mx = fmaxf(m0, m1);
    #pragma unroll
    for(int off = 16; off; off >>= 1) mx = fmaxf(mx, __shfl_xor_sync(0xffffffffu, mx, off));
    float sm = s0*expf(m0 - mx) + s1*expf(m1 - mx);
    #pragma unroll
    for(int off = 16; off; off >>= 1) sm += __shfl_xor_sync(0xffffffffu, sm, off);
    if (lane == 0){ g_smax[w] = mx; g_sinv[w] = 1.0f/sm; }
}

// partial o_k with inline softmax; embC slot: 0/1 -> g_emb, 2 -> emb3 (d_out)
__global__ void __launch_bounds__(256) k_o(
        int slot, const float* __restrict__ emb3, const float* __restrict__ gp,
        float* __restrict__ psoft_out){
    int b = blockIdx.y, c = blockIdx.x;
    const float* emb = (slot < 2) ? g_emb + (size_t)slot*EMB_SZ : emb3;
    __shared__ float sp[OCHUNK];
    __shared__ float4 sacc[4][64];
    int t = threadIdx.x, rg = t >> 6, d4 = t & 63;
    int m0 = c*OCHUNK;
    if (t < OCHUNK){
        float mx = g_smax[b], inv = g_sinv[b];
        float p = expf(g_logit[b*MM + m0 + t] - mx)*inv;
        if (psoft_out) psoft_out[b*MM + m0 + t] = p;
        sp[t] = p * gp[b*MM + m0 + t];
    }
    __syncthreads();
    const float4* base = reinterpret_cast<const float4*>(emb + ((size_t)b*MM + m0)*DD);
    float4 acc = make_float4(0.f, 0.f, 0.f, 0.f);
    #pragma unroll
    for(int mi = rg; mi < OCHUNK; mi += 4){
        float p = sp[mi];
        float4 v = base[(size_t)mi*64 + d4];
        acc.x += p*v.x; acc.y += p*v.y; acc.z += p*v.z; acc.w += p*v.w;
    }
    sacc[rg][d4] = acc;
    __syncthreads();
    if (t < 64){
        float4 a0 = sacc[0][t], a1 = sacc[1][t], a2 = sacc[2][t], a3 = sacc[3][t];
        float4 r;
        r.x = a0.x + a1.x + a2.x + a3.x;
        r.y = a0.y + a1.y + a2.y + a3.y;
        r.z = a0.z + a1.z + a2.z + a3.z;
        r.w = a0.w + a1.w + a2.w + a3.w;
        reinterpret_cast<float4*>(g_part + (size_t)c*BD + b*DD)[t] = r;
    }
}

// uf += reduced partials; optionally also write to d_out
__global__ void k_uf_add(float* __restrict__ out){
    int b = blockIdx.x, d = threadIdx.x;
    float o = 0.f;
    #pragma unroll
    for(int c = 0; c < NOB; ++c) o += g_part[c*BD + b*DD + d];
    float v = g_uf[b*DD + d] + o;
    g_uf[b*DD + d] = v;
    if (out) out[b*DD + d] = v;
}

// ---------------- launcher ----------------
extern "C" void kernel_launch(void* const* d_in, const int* in_sizes, int n_in,
                              void* d_out, int out_size){
    const int*   story = (const int*)  d_in[0];
    const int*   kb    = (const int*)  d_in[1];
    const int*   cl    = (const int*)  d_in[2];
    const float* hist  = (const float*)d_in[4];
    const float* qv    = (const float*)d_in[5];
    const float* gp    = (const float*)d_in[6];
    const float* C     = (const float*)d_in[7];

    float* out        = (float*)d_out;
    float* out_psoft  = out;                 // (B, M)
    float* out_logits = out + BM;            // (B, M)
    float* out_uf     = out + 2*BM;          // (B, D)
    float* out_emb3   = out + 2*BM + BD;     // (B, M, D) = m_story[-1]

    // Dead-code note: the reference's 3-layer loop never reaches any output;
    // only the layer-invariant embeddings + the query_vector pointer loop matter.
    // emb[0] is only used in hop-0 logits, which are linear in the gather ->
    // computed via tdot/hdot instead of materializing emb[0].

    k_init<<<BB, DD>>>(qv);
    // embeddings h=3,2 (streamed stores), h=1 last with cached stores (L2-warm for o0)
    k_embed<<<dim3(NEB, BB), 256>>>(2, 1, story, kb, cl, hist, C + (size_t)3*VV*DD, out_emb3);
    k_embed<<<dim3(NEB, BB), 256>>>(1, 1, story, kb, cl, hist, C + (size_t)2*VV*DD, out_emb3);
    k_embed<<<dim3(NEB, BB), 256>>>(0, 0, story, kb, cl, hist, C + (size_t)1*VV*DD, out_emb3);

    // hop 0: tdot/hdot path (no emb[0])
    k_tdot<<<VV/64, 256>>>(C);
    k_hdot<<<BB, 256>>>(hist);
    k_logit_fast<<<dim3(NLB, BB), 64>>>(story, kb, cl, gp);
    k_stats<<<1, 512>>>();
    k_o<<<dim3(NOB, BB), 256>>>(0, out_emb3, gp, nullptr);   // embC = emb[1]
    k_uf_add<<<BB, DD>>>(nullptr);

    // hop 1: logit streams emb[1] (L2-hot from o0)
    k_logit<<<dim3(NLB, BB), 256>>>(0, gp, nullptr);
    k_stats<<<1, 512>>>();
    k_o<<<dim3(NOB, BB), 256>>>(1, out_emb3, gp, nullptr);   // embC = emb[2]
    k_uf_add<<<BB, DD>>>(nullptr);

    // hop 2: logit streams emb[2] (L2-hot from o1); writes logits; o writes psoft; uf -> out
    k_logit<<<dim3(NLB, BB), 256>>>(1, gp, out_logits);
    k_stats<<<1, 512>>>();
    k_o<<<dim3(NOB, BB), 256>>>(2, out_emb3, gp, out_psoft); // embC = emb[3] (d_out)
    k_uf_add<<<BB, DD>>>(out_uf);
}